// round 4
// baseline (speedup 1.0000x reference)
#include <cuda_runtime.h>

#define BATCH 4096
#define N_AG  32
#define F_IN  256
#define F_OUT 128

// Scratch (device-global: no allocation allowed)
__device__ float g_z[BATCH * F_OUT];       // 2 MiB

// ---------- packed f32x2 helpers (SASS FFMA2 path, PTX-only) ----------
__device__ __forceinline__ unsigned long long pack2(float a, float b) {
    unsigned long long r;
    asm("mov.b64 %0, {%1, %2};" : "=l"(r) : "f"(a), "f"(b));
    return r;
}
__device__ __forceinline__ unsigned long long fma2(unsigned long long a,
                                                   unsigned long long b,
                                                   unsigned long long c) {
    unsigned long long d;
    asm("fma.rn.f32x2 %0, %1, %2, %3;" : "=l"(d) : "l"(a), "l"(b), "l"(c));
    return d;
}
__device__ __forceinline__ float2 unpack2(unsigned long long v) {
    float2 f;
    asm("mov.b64 {%0, %1}, %2;" : "=f"(f.x), "=f"(f.y) : "l"(v));
    return f;
}

// ================= K_A: mean over agents + 2-layer MLP -> g_z =================
// grid 1024 x 256 threads; block owns 4 batch elements.
#define TBA 4
__global__ __launch_bounds__(256) void kA_mean_mlp(
    const float* __restrict__ in,      // [BATCH, N_AG, F_IN]
    const float* __restrict__ lin_w,   // [F_IN, F_OUT]
    const float* __restrict__ hgcn_b,  // [F_OUT]
    const float* __restrict__ out_w,   // [F_OUT, F_OUT]
    const float* __restrict__ out_b)   // [F_OUT]
{
    __shared__ float sm[TBA][F_IN];    // 4 KB
    __shared__ float sy[TBA][F_OUT];   // 2 KB

    const int t  = threadIdx.x;
    const int B0 = blockIdx.x * TBA;

    // ---- Phase A: mean (identical memory pattern to measured k1) ----
    {
        const int f4 = t & 63;          // 64 float4 per row
        const int bi = t >> 6;          // batch-in-block 0..3
        const float4* p =
            (const float4*)(in + (size_t)(B0 + bi) * N_AG * F_IN) + f4;
        float4 a0 = {0,0,0,0}, a1 = {0,0,0,0}, a2 = {0,0,0,0}, a3 = {0,0,0,0};
        #pragma unroll
        for (int a = 0; a < N_AG; a += 4) {
            float4 v0 = p[(a + 0) * (F_IN / 4)];
            float4 v1 = p[(a + 1) * (F_IN / 4)];
            float4 v2 = p[(a + 2) * (F_IN / 4)];
            float4 v3 = p[(a + 3) * (F_IN / 4)];
            a0.x += v0.x; a0.y += v0.y; a0.z += v0.z; a0.w += v0.w;
            a1.x += v1.x; a1.y += v1.y; a1.z += v1.z; a1.w += v1.w;
            a2.x += v2.x; a2.y += v2.y; a2.z += v2.z; a2.w += v2.w;
            a3.x += v3.x; a3.y += v3.y; a3.z += v3.z; a3.w += v3.w;
        }
        float4 r;
        r.x = ((a0.x + a1.x) + (a2.x + a3.x)) * (1.0f / N_AG);
        r.y = ((a0.y + a1.y) + (a2.y + a3.y)) * (1.0f / N_AG);
        r.z = ((a0.z + a1.z) + (a2.z + a3.z)) * (1.0f / N_AG);
        r.w = ((a0.w + a1.w) + (a2.w + a3.w)) * (1.0f / N_AG);
        ((float4*)sm[bi])[f4] = r;
    }
    __syncthreads();

    const int j  = t & (F_OUT - 1);   // column 0..127
    const int r0 = (t >> 7) * 2;      // rows {0,1} or {2,3}

    // ---- Phase B: y = m @ lin_w + hgcn_bias (packed f32x2 over k-pairs) ----
    {
        unsigned long long acc0 = pack2(0.f, 0.f);
        unsigned long long acc1 = pack2(0.f, 0.f);
        #pragma unroll 4
        for (int k = 0; k < F_IN; k += 2) {
            unsigned long long wp =
                pack2(lin_w[(k + 0) * F_OUT + j], lin_w[(k + 1) * F_OUT + j]);
            unsigned long long m0 = *(const unsigned long long*)&sm[r0 + 0][k];
            unsigned long long m1 = *(const unsigned long long*)&sm[r0 + 1][k];
            acc0 = fma2(m0, wp, acc0);
            acc1 = fma2(m1, wp, acc1);
        }
        float hb = hgcn_b[j];
        float2 p0 = unpack2(acc0), p1 = unpack2(acc1);
        sy[r0 + 0][j] = p0.x + p0.y + hb;
        sy[r0 + 1][j] = p1.x + p1.y + hb;
    }
    __syncthreads();

    // ---- Phase C: z = relu(y @ out_w + out_b) -> g_z ----
    {
        unsigned long long acc0 = pack2(0.f, 0.f);
        unsigned long long acc1 = pack2(0.f, 0.f);
        #pragma unroll 4
        for (int k = 0; k < F_OUT; k += 2) {
            unsigned long long wp =
                pack2(out_w[(k + 0) * F_OUT + j], out_w[(k + 1) * F_OUT + j]);
            unsigned long long y0 = *(const unsigned long long*)&sy[r0 + 0][k];
            unsigned long long y1 = *(const unsigned long long*)&sy[r0 + 1][k];
            acc0 = fma2(y0, wp, acc0);
            acc1 = fma2(y1, wp, acc1);
        }
        float ob = out_b[j];
        float2 p0 = unpack2(acc0), p1 = unpack2(acc1);
        float v0 = p0.x + p0.y + ob;
        float v1 = p1.x + p1.y + ob;
        g_z[(size_t)(B0 + r0 + 0) * F_OUT + j] = v0 > 0.f ? v0 : 0.f;
        g_z[(size_t)(B0 + r0 + 1) * F_OUT + j] = v1 > 0.f ? v1 : 0.f;
    }
}

// ================= K_B: broadcast z to 32 agent rows =================
// grid 2048 x 256; block owns 2 batch elements = 2048 contiguous float4.
__global__ __launch_bounds__(256) void kB_bcast(float* __restrict__ out)
{
    const int t  = threadIdx.x;
    const int b0 = blockIdx.x * 2;
    float4* out4 = (float4*)out + (size_t)b0 * N_AG * (F_OUT / 4);
    const float4* z4 = (const float4*)g_z + (size_t)b0 * (F_OUT / 4);

    // cache the two z rows in registers once (each thread needs 2 values)
    const int f4a = t & 31;         // float4 index in row
    const int ba  = t >> 5 >= 4 ? 1 : 0; // not used; keep simple below
    (void)ba;

    #pragma unroll 8
    for (int o = t; o < 2 * N_AG * (F_OUT / 4); o += 256) {
        int b  = o >> 10;           // / (N_AG * F_OUT/4)
        int f4 = o & 31;
        out4[o] = z4[b * (F_OUT / 4) + f4];   // L2-resident read
    }
    (void)f4a;
}

extern "C" void kernel_launch(void* const* d_in, const int* in_sizes, int n_in,
                              void* d_out, int out_size) {
    const float* in     = (const float*)d_in[0];
    const float* lin_w  = (const float*)d_in[1];
    const float* hgcn_b = (const float*)d_in[2];
    const float* out_w  = (const float*)d_in[3];
    const float* out_b  = (const float*)d_in[4];
    // d_in[5], d_in[6]: dense incidence indices, analytically folded.
    float* out = (float*)d_out;

    kA_mean_mlp<<<BATCH / TBA, 256>>>(in, lin_w, hgcn_b, out_w, out_b);
    kB_bcast   <<<BATCH / 2,   256>>>(out);
}